// round 2
// baseline (speedup 1.0000x reference)
#include <cuda_runtime.h>
#include <cuda_bf16.h>

// ---------------------------------------------------------------------------
// CavAttention fused kernel (Round 1: fp32 SIMT baseline, fully fused)
//
// Shapes: x (B=2, L=5, H=48, W=176, C=256), HEADS=8, DHEAD=32, INNER=256.
// One CTA processes GPB=16 (b,h,w) groups = 80 tokens end-to-end:
//   1) load x slab [80,256] to smem
//   2) per head: GEMM [80,256]x[256,96] -> q|k|v slab; masked softmax over L=5;
//      P@V accumulated into attention-output slab [80,256] in smem
//   3) output GEMM [80,256]x[256,256] + bias, transposed store to (B,L,H,W,C)
// ---------------------------------------------------------------------------

#define B_     2
#define L_     5
#define H_     48
#define W_     176
#define C_     256
#define HEADS_ 8
#define DHEAD_ 32
#define INNER_ 256
#define NQKV_  768
#define HW_    (H_ * W_)        // 8448
#define NGROUPS_ (B_ * HW_)     // 16896

#define GPB    16               // groups per block
#define MROWS  (GPB * L_)       // 80 tokens per block
#define NTHREADS 256
#define NBLOCKS (NGROUPS_ / GPB) // 1056

#define XS_STRIDE  257          // pad 256 -> 257 (conflict-free column reads)
#define QKV_STRIDE 100          // pad 96 -> 100
#define WB_STRIDE  132          // pad 128 -> 132 (gemm2); gemm1 uses stride 100

// shared memory layout (floats)
#define XS_ELEMS   (MROWS * XS_STRIDE)    // 20560
#define OS_ELEMS   (MROWS * XS_STRIDE)    // 20560
#define QKV_ELEMS  (MROWS * QKV_STRIDE)   // 8000
#define WB_ELEMS   (32 * WB_STRIDE)       // 4224
#define SC_ELEMS   (GPB * 25)             // 400
#define MS_ELEMS   (GPB * L_)             // 80 (ints)
#define SMEM_FLOATS (XS_ELEMS + OS_ELEMS + QKV_ELEMS + WB_ELEMS + SC_ELEMS)
#define SMEM_BYTES  (SMEM_FLOATS * 4 + MS_ELEMS * 4)   // 215,296 B

__global__ __launch_bounds__(NTHREADS, 1)
void cav_attention_fused(const float* __restrict__ x,
                         const int*   __restrict__ mask,
                         const float* __restrict__ wqkv,
                         const float* __restrict__ wout,
                         const float* __restrict__ bout,
                         float*       __restrict__ out) {
    extern __shared__ float sm[];
    float* xs   = sm;                         // [80][257] input tokens
    float* os   = xs + XS_ELEMS;              // [80][257] attention output
    float* qkvh = os + OS_ELEMS;              // [80][100] per-head q|k|v
    float* wb   = qkvh + QKV_ELEMS;           // [32][<=132] staged weights
    float* sc   = wb + WB_ELEMS;              // [16][5][5] scores/probs
    int*   ms   = (int*)(sc + SC_ELEMS);      // [16][5] mask

    const int tid = threadIdx.x;
    const int tx  = tid & 15;                 // N direction (16)
    const int ty  = tid >> 4;                 // M direction (16)
    const int g0  = blockIdx.x * GPB;

    // ---- load mask for the 16 groups: mask layout (B,H,W,1,L) = [g][j] ----
    for (int e = tid; e < GPB * L_; e += NTHREADS) {
        int g = g0 + e / L_;
        int j = e % L_;
        ms[e] = mask[g * L_ + j];
    }

    // ---- load x tokens: row = g_local*5 + l ; x flat = ((b*L+l)*HW + hw)*C + c
    for (int e = tid; e < MROWS * (C_ / 4); e += NTHREADS) {
        int row = e / (C_ / 4);
        int c4  = (e % (C_ / 4)) * 4;
        int g   = g0 + row / L_;
        int l   = row % L_;
        int b   = g / HW_;
        int hw  = g % HW_;
        const float4 v = *(const float4*)(x + ((size_t)((b * L_ + l) * HW_ + hw)) * C_ + c4);
        float* dst = xs + row * XS_STRIDE + c4;
        dst[0] = v.x; dst[1] = v.y; dst[2] = v.z; dst[3] = v.w;
    }
    __syncthreads();

    const float scale = 0.17677669529663687f;  // 1/sqrt(32)

    // hoisted row pointers for the M tiles (rows ty, ty+16, ..., ty+64)
    const float* xrow[5];
    #pragma unroll
    for (int i = 0; i < 5; ++i) xrow[i] = xs + (ty + 16 * i) * XS_STRIDE;
    const float* orow[5];
    #pragma unroll
    for (int i = 0; i < 5; ++i) orow[i] = os + (ty + 16 * i) * XS_STRIDE;

    // ======================= per-head QKV GEMM + attention ==================
    for (int head = 0; head < HEADS_; ++head) {
        float acc[5][6];
        #pragma unroll
        for (int i = 0; i < 5; ++i)
            #pragma unroll
            for (int j = 0; j < 6; ++j) acc[i][j] = 0.f;

        for (int k0 = 0; k0 < C_; k0 += 32) {
            // stage 32 x 96 weight tile: cols {q,k,v} for this head
            for (int e = tid; e < 32 * 96; e += NTHREADS) {
                int kk = e / 96, n = e % 96;
                int part = n >> 5;                       // 0:q 1:k 2:v
                int col  = part * INNER_ + head * DHEAD_ + (n & 31);
                wb[kk * QKV_STRIDE + n] = wqkv[(k0 + kk) * NQKV_ + col];
            }
            __syncthreads();

            #pragma unroll 8
            for (int kk = 0; kk < 32; ++kk) {
                float a[5], bv[6];
                #pragma unroll
                for (int i = 0; i < 5; ++i) a[i] = xrow[i][k0 + kk];
                const float* wr = wb + kk * QKV_STRIDE + tx;
                #pragma unroll
                for (int j = 0; j < 6; ++j) bv[j] = wr[16 * j];
                #pragma unroll
                for (int i = 0; i < 5; ++i)
                    #pragma unroll
                    for (int j = 0; j < 6; ++j)
                        acc[i][j] = fmaf(a[i], bv[j], acc[i][j]);
            }
            __syncthreads();
        }

        // write q|k|v slab
        #pragma unroll
        for (int i = 0; i < 5; ++i)
            #pragma unroll
            for (int j = 0; j < 6; ++j)
                qkvh[(ty + 16 * i) * QKV_STRIDE + tx + 16 * j] = acc[i][j];
        __syncthreads();

        // ---- scores: s[g][i][j] = scale * q_i . k_j  (masked) ----
        for (int e = tid; e < GPB * 25; e += NTHREADS) {
            int g = e / 25, r = e % 25, i = r / 5, j = r % 5;
            float s;
            if (ms[g * 5 + j] == 0) {
                s = -1e30f;
            } else {
                const float* qr = qkvh + (g * 5 + i) * QKV_STRIDE;
                const float* kr = qkvh + (g * 5 + j) * QKV_STRIDE + 32;
                s = 0.f;
                #pragma unroll
                for (int d = 0; d < 32; ++d) s = fmaf(qr[d], kr[d], s);
                s *= scale;
            }
            sc[e] = s;
        }
        __syncthreads();

        // ---- softmax over j per (g,i): 80 rows ----
        if (tid < MROWS) {
            int g = tid / 5, i = tid % 5;
            float* r = sc + g * 25 + i * 5;
            float mx = r[0];
            #pragma unroll
            for (int j = 1; j < 5; ++j) mx = fmaxf(mx, r[j]);
            float ev[5], s = 0.f;
            #pragma unroll
            for (int j = 0; j < 5; ++j) { ev[j] = __expf(r[j] - mx); s += ev[j]; }
            float inv = 1.f / s;
            #pragma unroll
            for (int j = 0; j < 5; ++j) r[j] = ev[j] * inv;
        }
        __syncthreads();

        // ---- o[row][d] = sum_j p * v_j[d], stored at column head*32+d ----
        for (int e = tid; e < MROWS * DHEAD_; e += NTHREADS) {
            int row = e >> 5, d = e & 31;
            int g = row / 5, i = row % 5;
            const float* p = sc + g * 25 + i * 5;
            float o = 0.f;
            #pragma unroll
            for (int j = 0; j < 5; ++j)
                o = fmaf(p[j], qkvh[(g * 5 + j) * QKV_STRIDE + 64 + d], o);
            os[row * XS_STRIDE + head * DHEAD_ + d] = o;
        }
        __syncthreads();   // qkvh reused next head
    }

    // ======================= output GEMM + bias + transposed store ==========
    for (int nc = 0; nc < 2; ++nc) {               // two 128-col chunks
        float acc[5][8];
        #pragma unroll
        for (int i = 0; i < 5; ++i)
            #pragma unroll
            for (int j = 0; j < 8; ++j) acc[i][j] = 0.f;

        for (int k0 = 0; k0 < C_; k0 += 32) {
            for (int e = tid; e < 32 * 128; e += NTHREADS) {
                int kk = e >> 7, n = e & 127;
                wb[kk * WB_STRIDE + n] = wout[(k0 + kk) * INNER_ + nc * 128 + n];
            }
            __syncthreads();

            #pragma unroll 8
            for (int kk = 0; kk < 32; ++kk) {
                float a[5], bv[8];
                #pragma unroll
                for (int i = 0; i < 5; ++i) a[i] = orow[i][k0 + kk];
                const float* wr = wb + kk * WB_STRIDE + tx;
                #pragma unroll
                for (int j = 0; j < 8; ++j) bv[j] = wr[16 * j];
                #pragma unroll
                for (int i = 0; i < 5; ++i)
                    #pragma unroll
                    for (int j = 0; j < 8; ++j)
                        acc[i][j] = fmaf(a[i], bv[j], acc[i][j]);
            }
            __syncthreads();
        }

        // epilogue: out flat = ((b*L+l)*HW + hw)*C + col  (same layout as x)
        #pragma unroll
        for (int i = 0; i < 5; ++i) {
            int row = ty + 16 * i;
            int g   = g0 + row / 5;
            int l   = row % 5;
            int b   = g / HW_;
            int hw  = g % HW_;
            size_t base = ((size_t)((b * L_ + l) * HW_ + hw)) * C_;
            #pragma unroll
            for (int j = 0; j < 8; ++j) {
                int col = nc * 128 + tx + 16 * j;
                out[base + col] = acc[i][j] + bout[col];
            }
        }
    }
}

extern "C" void kernel_launch(void* const* d_in, const int* in_sizes, int n_in,
                              void* d_out, int out_size) {
    const float* x    = (const float*)d_in[0];
    const int*   mask = (const int*)d_in[1];
    const float* wqkv = (const float*)d_in[2];
    const float* wout = (const float*)d_in[3];
    const float* bout = (const float*)d_in[4];
    float*       out  = (float*)d_out;

    cudaFuncSetAttribute(cav_attention_fused,
                         cudaFuncAttributeMaxDynamicSharedMemorySize, SMEM_BYTES);
    cav_attention_fused<<<NBLOCKS, NTHREADS, SMEM_BYTES>>>(x, mask, wqkv, wout, bout, out);
}